// round 1
// baseline (speedup 1.0000x reference)
#include <cuda_runtime.h>

// CBOW negative-sampling loss:
//   src[b]   = sum_c ctx_emb[contexts[b,c]]                       (B x D)
//   pred[b,k]= dot(src[b], neg_emb[focus[b,k]])                   (B x K)
//   bce      = w * (softplus(pred) - pred*y)
//   out      = mean_b( sum_k bce / sum_k w )
//
// B=16384, C=10, K=8, D=128, VOCAB=100000. Output: 1 float.

#define NB     16384
#define NC     10
#define NK     8
#define NDIM   128
#define WPB    8          // warps per block (1 warp = 1 example)

__global__ void cbow_zero_out(float* __restrict__ out) {
    if (threadIdx.x == 0) out[0] = 0.0f;
}

__global__ __launch_bounds__(WPB * 32, 4)
void cbow_kernel(const int*   __restrict__ contexts,   // [B, C]
                 const int*   __restrict__ focus,      // [B, K]
                 const float* __restrict__ weight,     // [B, K]
                 const float* __restrict__ labels,     // [B, K]
                 const float* __restrict__ ctx_emb,    // [VOCAB, D]
                 const float* __restrict__ neg_emb,    // [VOCAB, D]
                 float*       __restrict__ out)
{
    const int warp = threadIdx.x >> 5;
    const int lane = threadIdx.x & 31;
    const int b    = blockIdx.x * WPB + warp;

    // ---- gather + sum-pool context embeddings; lane owns dims [4*lane, 4*lane+4) ----
    // Load all 10 indices up front (broadcast loads), then issue 10 independent
    // float4 gathers for max memory-level parallelism.
    int cidx[NC];
    #pragma unroll
    for (int c = 0; c < NC; c++) cidx[c] = contexts[b * NC + c];

    float4 src = make_float4(0.f, 0.f, 0.f, 0.f);
    #pragma unroll
    for (int c = 0; c < NC; c++) {
        const float4* row = reinterpret_cast<const float4*>(
            ctx_emb + (size_t)cidx[c] * NDIM);
        float4 e = __ldg(row + lane);
        src.x += e.x; src.y += e.y; src.z += e.z; src.w += e.w;
    }

    // ---- K target gathers + dots + stable weighted BCE ----
    int fidx[NK];
    #pragma unroll
    for (int k = 0; k < NK; k++) fidx[k] = focus[b * NK + k];

    float loss = 0.f, wsum = 0.f;
    #pragma unroll
    for (int k = 0; k < NK; k++) {
        const float4* row = reinterpret_cast<const float4*>(
            neg_emb + (size_t)fidx[k] * NDIM);
        float4 t = __ldg(row + lane);
        float p = src.x * t.x + src.y * t.y + src.z * t.z + src.w * t.w;
        // warp butterfly reduction: all lanes end with full dot product
        #pragma unroll
        for (int s = 16; s > 0; s >>= 1)
            p += __shfl_xor_sync(0xffffffffu, p, s);

        float w = weight[b * NK + k];   // broadcast load (same addr all lanes)
        float y = labels[b * NK + k];
        // logaddexp(0, p) = max(p,0) + log1p(exp(-|p|))  (stable for |p|~100)
        float sp = fmaxf(p, 0.f) + log1pf(__expf(-fabsf(p)));
        loss += w * (sp - p * y);
        wsum += w;
    }

    // per_row = mean_k(bce)*K / sum_k(w) = loss / wsum ; batch mean -> /NB
    float contrib = loss / wsum * (1.0f / (float)NB);

    __shared__ float sh[WPB];
    if (lane == 0) sh[warp] = contrib;
    __syncthreads();
    if (threadIdx.x == 0) {
        float s = 0.f;
        #pragma unroll
        for (int i = 0; i < WPB; i++) s += sh[i];
        atomicAdd(out, s);
    }
}

extern "C" void kernel_launch(void* const* d_in, const int* in_sizes, int n_in,
                              void* d_out, int out_size) {
    const int*   contexts = (const int*)  d_in[0];   // [B, C] int32
    const int*   focus    = (const int*)  d_in[1];   // [B, K] int32
    const float* weight   = (const float*)d_in[2];   // [B, K] f32
    const float* labels   = (const float*)d_in[3];   // [B, K] f32
    const float* ctx_emb  = (const float*)d_in[4];   // [VOCAB, D] f32
    const float* neg_emb  = (const float*)d_in[5];   // [VOCAB, D] f32
    float* out = (float*)d_out;

    cbow_zero_out<<<1, 32>>>(out);
    cbow_kernel<<<NB / WPB, WPB * 32>>>(contexts, focus, weight, labels,
                                        ctx_emb, neg_emb, out);
}

// round 2
// speedup vs baseline: 1.0280x; 1.0280x over previous
#include <cuda_runtime.h>

// CBOW negative-sampling loss:
//   src[b]   = sum_c ctx_emb[contexts[b,c]]                       (B x D)
//   pred[b,k]= dot(src[b], neg_emb[focus[b,k]])                   (B x K)
//   bce      = w * (softplus(pred) - pred*y)
//   out      = mean_b( sum_k bce / sum_k w )
//
// B=16384, C=10, K=8, D=128, VOCAB=100000. Output: 1 float.
//
// R2: occupancy push. 48-reg cap (5 blocks/SM -> 62.5% occ) with batched
// gathers sized to fit the register budget without spills.

#define NB     16384
#define NC     10
#define NK     8
#define NDIM   128
#define WPB    8          // warps per block (1 warp = 1 example)

__global__ void cbow_zero_out(float* __restrict__ out) {
    if (threadIdx.x == 0) out[0] = 0.0f;
}

__device__ __forceinline__ float warp_sum(float p) {
    #pragma unroll
    for (int s = 16; s > 0; s >>= 1)
        p += __shfl_xor_sync(0xffffffffu, p, s);
    return p;
}

__global__ __launch_bounds__(WPB * 32, 5)
void cbow_kernel(const int*   __restrict__ contexts,   // [B, C]
                 const int*   __restrict__ focus,      // [B, K]
                 const float* __restrict__ weight,     // [B, K]
                 const float* __restrict__ labels,     // [B, K]
                 const float* __restrict__ ctx_emb,    // [VOCAB, D]
                 const float* __restrict__ neg_emb,    // [VOCAB, D]
                 float*       __restrict__ out)
{
    const int warp = threadIdx.x >> 5;
    const int lane = threadIdx.x & 31;
    const int b    = blockIdx.x * WPB + warp;

    const int* ctxp = contexts + b * NC;
    float4 src = make_float4(0.f, 0.f, 0.f, 0.f);

    // ---- context gathers in two batches of 5 (keeps <=5 float4 loads live) ----
    #pragma unroll
    for (int half = 0; half < 2; half++) {
        int i0 = ctxp[half * 5 + 0];
        int i1 = ctxp[half * 5 + 1];
        int i2 = ctxp[half * 5 + 2];
        int i3 = ctxp[half * 5 + 3];
        int i4 = ctxp[half * 5 + 4];
        float4 e0 = __ldg(reinterpret_cast<const float4*>(ctx_emb + (size_t)i0 * NDIM) + lane);
        float4 e1 = __ldg(reinterpret_cast<const float4*>(ctx_emb + (size_t)i1 * NDIM) + lane);
        float4 e2 = __ldg(reinterpret_cast<const float4*>(ctx_emb + (size_t)i2 * NDIM) + lane);
        float4 e3 = __ldg(reinterpret_cast<const float4*>(ctx_emb + (size_t)i3 * NDIM) + lane);
        float4 e4 = __ldg(reinterpret_cast<const float4*>(ctx_emb + (size_t)i4 * NDIM) + lane);
        src.x += e0.x + e1.x + e2.x + e3.x + e4.x;
        src.y += e0.y + e1.y + e2.y + e3.y + e4.y;
        src.z += e0.z + e1.z + e2.z + e3.z + e4.z;
        src.w += e0.w + e1.w + e2.w + e3.w + e4.w;
    }

    // ---- target gathers + BCE in two batches of 4 ----
    const int* fp = focus + b * NK;
    float loss = 0.f, wsum = 0.f;

    #pragma unroll
    for (int half = 0; half < 2; half++) {
        int j0 = fp[half * 4 + 0];
        int j1 = fp[half * 4 + 1];
        int j2 = fp[half * 4 + 2];
        int j3 = fp[half * 4 + 3];
        float4 t0 = __ldg(reinterpret_cast<const float4*>(neg_emb + (size_t)j0 * NDIM) + lane);
        float4 t1 = __ldg(reinterpret_cast<const float4*>(neg_emb + (size_t)j1 * NDIM) + lane);
        float4 t2 = __ldg(reinterpret_cast<const float4*>(neg_emb + (size_t)j2 * NDIM) + lane);
        float4 t3 = __ldg(reinterpret_cast<const float4*>(neg_emb + (size_t)j3 * NDIM) + lane);

        float p0 = src.x * t0.x + src.y * t0.y + src.z * t0.z + src.w * t0.w;
        float p1 = src.x * t1.x + src.y * t1.y + src.z * t1.z + src.w * t1.w;
        float p2 = src.x * t2.x + src.y * t2.y + src.z * t2.z + src.w * t2.w;
        float p3 = src.x * t3.x + src.y * t3.y + src.z * t3.z + src.w * t3.w;
        p0 = warp_sum(p0);
        p1 = warp_sum(p1);
        p2 = warp_sum(p2);
        p3 = warp_sum(p3);

        // uniform vector loads of weights / labels for these 4 targets
        float4 w4 = __ldg(reinterpret_cast<const float4*>(weight + b * NK) + half);
        float4 y4 = __ldg(reinterpret_cast<const float4*>(labels + b * NK) + half);

        // logaddexp(0,p) = max(p,0) + log1p(exp(-|p|))
        float sp0 = fmaxf(p0, 0.f) + log1pf(__expf(-fabsf(p0)));
        float sp1 = fmaxf(p1, 0.f) + log1pf(__expf(-fabsf(p1)));
        float sp2 = fmaxf(p2, 0.f) + log1pf(__expf(-fabsf(p2)));
        float sp3 = fmaxf(p3, 0.f) + log1pf(__expf(-fabsf(p3)));

        loss += w4.x * (sp0 - p0 * y4.x);
        loss += w4.y * (sp1 - p1 * y4.y);
        loss += w4.z * (sp2 - p2 * y4.z);
        loss += w4.w * (sp3 - p3 * y4.w);
        wsum += w4.x + w4.y + w4.z + w4.w;
    }

    // per_row = sum(bce)/sum(w); batch mean -> /NB
    float contrib = loss / wsum * (1.0f / (float)NB);

    __shared__ float sh[WPB];
    if (lane == 0) sh[warp] = contrib;
    __syncthreads();
    if (threadIdx.x == 0) {
        float s = 0.f;
        #pragma unroll
        for (int i = 0; i < WPB; i++) s += sh[i];
        atomicAdd(out, s);
    }
}

extern "C" void kernel_launch(void* const* d_in, const int* in_sizes, int n_in,
                              void* d_out, int out_size) {
    const int*   contexts = (const int*)  d_in[0];   // [B, C] int32
    const int*   focus    = (const int*)  d_in[1];   // [B, K] int32
    const float* weight   = (const float*)d_in[2];   // [B, K] f32
    const float* labels   = (const float*)d_in[3];   // [B, K] f32
    const float* ctx_emb  = (const float*)d_in[4];   // [VOCAB, D] f32
    const float* neg_emb  = (const float*)d_in[5];   // [VOCAB, D] f32
    float* out = (float*)d_out;

    cbow_zero_out<<<1, 32>>>(out);
    cbow_kernel<<<NB / WPB, WPB * 32>>>(contexts, focus, weight, labels,
                                        ctx_emb, neg_emb, out);
}

// round 3
// speedup vs baseline: 1.1456x; 1.1144x over previous
#include <cuda_runtime.h>

// CBOW negative-sampling loss:
//   src[b]   = sum_c ctx_emb[contexts[b,c]]                       (B x D)
//   pred[b,k]= dot(src[b], neg_emb[focus[b,k]])                   (B x K)
//   bce      = w * (softplus(pred) - pred*y)
//   out      = mean_b( sum_k bce / sum_k w )
//
// B=16384, C=10, K=8, D=128, VOCAB=100000. Output: 1 float.
//
// R3: instruction diet. Fast softplus (MUFU), merged 8-way butterfly
// reduction (16 shfl instead of 40, softplus 4x-replicated not 32x),
// vectorized index loads, full-MLP gathers.

#define NB     16384
#define NC     10
#define NK     8
#define NDIM   128
#define WPB    8          // warps per block (1 warp = 1 example)

__global__ void cbow_zero_out(float* __restrict__ out) {
    if (threadIdx.x == 0) out[0] = 0.0f;
}

// Butterfly step that merges two reduction trees: lanes with (lane & s)==0
// continue carrying x's partial sum, the others carry y's.
__device__ __forceinline__ float merge2(float x, float y, int s, int lane) {
    float xs = __shfl_xor_sync(0xffffffffu, x, s);
    float ys = __shfl_xor_sync(0xffffffffu, y, s);
    return (lane & s) ? (y + ys) : (x + xs);
}

__global__ __launch_bounds__(WPB * 32, 4)
void cbow_kernel(const int*   __restrict__ contexts,   // [B, C]
                 const int*   __restrict__ focus,      // [B, K]
                 const float* __restrict__ weight,     // [B, K]
                 const float* __restrict__ labels,     // [B, K]
                 const float* __restrict__ ctx_emb,    // [VOCAB, D]
                 const float* __restrict__ neg_emb,    // [VOCAB, D]
                 float*       __restrict__ out)
{
    const int warp = threadIdx.x >> 5;
    const int lane = threadIdx.x & 31;
    const int b    = blockIdx.x * WPB + warp;

    // ---- context indices: 5x int2 (row is 8B-aligned but not 16B) ----
    const int2* c2 = reinterpret_cast<const int2*>(contexts + b * NC);
    int2 ca = __ldg(c2 + 0), cb = __ldg(c2 + 1), cc = __ldg(c2 + 2),
         cd = __ldg(c2 + 3), ce = __ldg(c2 + 4);
    int ci[NC] = {ca.x, ca.y, cb.x, cb.y, cc.x, cc.y, cd.x, cd.y, ce.x, ce.y};

    // ---- 10 context gathers, all in flight; lane owns dims [4*lane,4*lane+4) ----
    float4 e[NC];
    #pragma unroll
    for (int c = 0; c < NC; c++)
        e[c] = __ldg(reinterpret_cast<const float4*>(ctx_emb + (size_t)ci[c] * NDIM) + lane);

    float4 src = make_float4(0.f, 0.f, 0.f, 0.f);
    #pragma unroll
    for (int c = 0; c < NC; c++) {
        src.x += e[c].x; src.y += e[c].y; src.z += e[c].z; src.w += e[c].w;
    }

    // ---- target indices: 2x int4 (row is 32B-aligned) ----
    const int4* f4 = reinterpret_cast<const int4*>(focus + b * NK);
    int4 fa = __ldg(f4 + 0), fb = __ldg(f4 + 1);
    int fi[NK] = {fa.x, fa.y, fa.z, fa.w, fb.x, fb.y, fb.z, fb.w};

    // ---- 8 target gathers, all in flight; per-lane partial dots ----
    float p[NK];
    #pragma unroll
    for (int k = 0; k < NK; k++) {
        float4 t = __ldg(reinterpret_cast<const float4*>(neg_emb + (size_t)fi[k] * NDIM) + lane);
        p[k] = src.x * t.x + src.y * t.y + src.z * t.z + src.w * t.w;
    }

    // ---- merged 8-way warp reduction (16 shfl total) ----
    // After the 3 merge stages, lane group g = lane>>2 carries p[bitrev3(g)];
    // the last 2 butterfly steps complete the 32-lane sum within each group.
    float m01 = merge2(p[0], p[1], 16, lane);
    float m23 = merge2(p[2], p[3], 16, lane);
    float m45 = merge2(p[4], p[5], 16, lane);
    float m67 = merge2(p[6], p[7], 16, lane);
    float n03 = merge2(m01, m23, 8, lane);
    float n47 = merge2(m45, m67, 8, lane);
    float q   = merge2(n03, n47, 4, lane);
    q += __shfl_xor_sync(0xffffffffu, q, 2);
    q += __shfl_xor_sync(0xffffffffu, q, 1);
    // q = full dot product pred[b,k], k = bitrev3(lane>>2), replicated x4.

    const int g = lane >> 2;
    const int k = ((g & 1) << 2) | (g & 2) | (g >> 2);   // bitrev3

    float w = __ldg(weight + b * NK + k);
    float y = __ldg(labels + b * NK + k);

    // softplus via MUFU: logaddexp(0,q) = max(q,0) + log(1 + exp(-|q|))
    float sp  = fmaxf(q, 0.f) + __logf(1.f + __expf(-fabsf(q)));
    float bce = w * (sp - q * y);

    // Warp-sum bce and w (each k replicated x4 -> both sums carry a x4
    // factor that cancels in the ratio).
    float ls = bce, ws = w;
    #pragma unroll
    for (int s = 16; s > 0; s >>= 1) {
        ls += __shfl_xor_sync(0xffffffffu, ls, s);
        ws += __shfl_xor_sync(0xffffffffu, ws, s);
    }
    float contrib = ls / ws * (1.0f / (float)NB);

    __shared__ float sh[WPB];
    if (lane == 0) sh[warp] = contrib;
    __syncthreads();
    if (threadIdx.x == 0) {
        float s = 0.f;
        #pragma unroll
        for (int i = 0; i < WPB; i++) s += sh[i];
        atomicAdd(out, s);
    }
}

extern "C" void kernel_launch(void* const* d_in, const int* in_sizes, int n_in,
                              void* d_out, int out_size) {
    const int*   contexts = (const int*)  d_in[0];   // [B, C] int32
    const int*   focus    = (const int*)  d_in[1];   // [B, K] int32
    const float* weight   = (const float*)d_in[2];   // [B, K] f32
    const float* labels   = (const float*)d_in[3];   // [B, K] f32
    const float* ctx_emb  = (const float*)d_in[4];   // [VOCAB, D] f32
    const float* neg_emb  = (const float*)d_in[5];   // [VOCAB, D] f32
    float* out = (float*)d_out;

    cbow_zero_out<<<1, 32>>>(out);
    cbow_kernel<<<NB / WPB, WPB * 32>>>(contexts, focus, weight, labels,
                                        ctx_emb, neg_emb, out);
}